// round 3
// baseline (speedup 1.0000x reference)
#include <cuda_runtime.h>
#include <cuda_bf16.h>

#define BB 8
#define CCH 512
#define LL1 1024
#define LL2 64
#define NHH 8

// ---------------- scratch (no allocations allowed) ----------------
// g_qkv doubles as cross-q storage: self qkv is dead after steps 5/6, so
// step 8 writes cq (16 MB) into the front of this 48 MB region.
__device__ float g_gn1[BB*CCH*LL1];        // 16 MB (gn of xf, reused for gn of xf2)
__device__ float g_qkv[BB*3*CCH*LL1];      // 48 MB (self qkv; later cross q)
__device__ float g_ipos[BB*CCH*LL1];       // 16 MB
__device__ float g_attnbuf[BB*CCH*LL1];    // 16 MB (self attn out, then cross attn out)
__device__ float g_xf2[BB*CCH*LL1];        // 16 MB
__device__ float g_cpos[BB*CCH*LL2];
__device__ float g_content[BB*CCH*LL2];
__device__ float g_kv[BB*2*CCH*LL2];

// ---------------- GroupNorm ----------------
// one block per (batch, group). optional fused epilogue: out = 0.5*(post + gn)
__global__ __launch_bounds__(256) void gn_kernel(
    const float* __restrict__ in, float* __restrict__ out,
    const float* __restrict__ g, const float* __restrict__ b,
    const float* __restrict__ post,
    int C, int Cg, int L, float eps)
{
    int G = C / Cg;
    int bi = blockIdx.x / G, gi = blockIdx.x % G;
    long base = (long)bi * C * L + (long)gi * Cg * L;
    int n = Cg * L;
    float s = 0.f, s2 = 0.f;
    for (int i = threadIdx.x; i < n; i += 256) {
        float v = in[base + i];
        s += v; s2 += v * v;
    }
    __shared__ float r1[256], r2[256];
    r1[threadIdx.x] = s; r2[threadIdx.x] = s2;
    __syncthreads();
    for (int off = 128; off > 0; off >>= 1) {
        if (threadIdx.x < off) {
            r1[threadIdx.x] += r1[threadIdx.x + off];
            r2[threadIdx.x] += r2[threadIdx.x + off];
        }
        __syncthreads();
    }
    float mean = r1[0] / n;
    float var  = r2[0] / n - mean * mean;
    float inv  = rsqrtf(var + eps);
    for (int i = threadIdx.x; i < n; i += 256) {
        int c = gi * Cg + i / L;
        float v = (in[base + i] - mean) * inv * g[c] + b[c];
        if (post) v = 0.5f * (post[base + i] + v);
        out[base + i] = v;
    }
}

// ---------------- batched SGEMM: Y[b] = A(MxK) @ X[b](KxN) + bias (+ res) ----------------
// 128x128 tile, BK=8, 256 threads, 8x8 per thread in 2x2 sub-blocks of 4.
__global__ __launch_bounds__(256) void sgemm128(
    const float* __restrict__ A, const float* __restrict__ Bx,
    const float* __restrict__ bias, const float* __restrict__ res,
    float* __restrict__ Y,
    int M, int N, int K, long x_bs, long y_bs, long r_bs)
{
    __shared__ float As[8][128];
    __shared__ float Bs[8][128];
    int bz = blockIdx.z;
    const float* X = Bx + (long)bz * x_bs;
    int m0 = blockIdx.y * 128, n0 = blockIdx.x * 128;
    int tid = threadIdx.x;
    int tx = tid & 15, ty = tid >> 4;
    float acc[8][8];
    #pragma unroll
    for (int i = 0; i < 8; i++)
        #pragma unroll
        for (int j = 0; j < 8; j++) acc[i][j] = 0.f;

    int aRow  = tid >> 1;       // 0..127
    int aColB = (tid & 1) * 4;  // 0 or 4
    int bRow  = tid >> 5;       // 0..7
    int bColB = (tid & 31) * 4; // 0..124

    for (int k0 = 0; k0 < K; k0 += 8) {
        float4 av = make_float4(0.f, 0.f, 0.f, 0.f);
        int am = m0 + aRow;
        if (am < M) av = *(const float4*)(A + (long)am * K + k0 + aColB);
        As[aColB + 0][aRow] = av.x;
        As[aColB + 1][aRow] = av.y;
        As[aColB + 2][aRow] = av.z;
        As[aColB + 3][aRow] = av.w;
        float4 bv = make_float4(0.f, 0.f, 0.f, 0.f);
        int bn = n0 + bColB;
        if (bn < N) bv = *(const float4*)(X + (long)(k0 + bRow) * N + bn);
        *(float4*)&Bs[bRow][bColB] = bv;
        __syncthreads();
        #pragma unroll
        for (int kk = 0; kk < 8; kk++) {
            float ra[8], rb[8];
            *(float4*)&ra[0] = *(const float4*)&As[kk][ty * 4];
            *(float4*)&ra[4] = *(const float4*)&As[kk][64 + ty * 4];
            *(float4*)&rb[0] = *(const float4*)&Bs[kk][tx * 4];
            *(float4*)&rb[4] = *(const float4*)&Bs[kk][64 + tx * 4];
            #pragma unroll
            for (int i = 0; i < 8; i++)
                #pragma unroll
                for (int j = 0; j < 8; j++)
                    acc[i][j] += ra[i] * rb[j];
        }
        __syncthreads();
    }
    #pragma unroll
    for (int i = 0; i < 8; i++) {
        int m = m0 + ((i < 4) ? ty * 4 + i : 64 + ty * 4 + (i - 4));
        if (m >= M) continue;
        float bvv = bias[m];
        #pragma unroll
        for (int j = 0; j < 8; j++) {
            int n = n0 + ((j < 4) ? tx * 4 + j : 64 + tx * 4 + (j - 4));
            if (n >= N) continue;
            float v = acc[i][j] + bvv;
            if (res) v += res[(long)bz * r_bs + (long)m * N + n];
            Y[(long)bz * y_bs + (long)m * N + n] = v;
        }
    }
}

// ---------------- flash-style attention ----------------
// Per block: one head (blockIdx.y), 64 queries (blockIdx.x). 128-ch q/k (content||pos),
// 64-ch v. Online softmax over s-tiles of 64.
// Layouts in smem: Qs[c][t] (128x64), Ks[c][s] (128x64), Vs[s][c] (64 x stride68),
// Ps[t][s] (64x64), reused as Os[c][t] (stride 65) for coalesced output.
#define VS_STRIDE 68
#define OS_STRIDE 65
#define ATTN_SMEM_FLOATS (8192 + 8192 + 64*VS_STRIDE + 64*OS_STRIDE)
#define ATTN_SMEM_BYTES (ATTN_SMEM_FLOATS * 4)

__global__ __launch_bounds__(256) void attn_kernel(
    const float* __restrict__ Qc, long qc_bs,
    const float* __restrict__ Qp, long qp_bs,
    const float* __restrict__ Kc, long kc_bs,
    const float* __restrict__ Kp, long kp_bs,
    const float* __restrict__ V,  long v_bs,
    float* __restrict__ O, long o_bs,
    int Lq, int Ls, float sc2)
{
    extern __shared__ float sm[];
    float* Qs = sm;
    float* Ks = sm + 8192;
    float* Vs = sm + 16384;
    float* Ps = sm + 16384 + 64 * VS_STRIDE;

    int hy = blockIdx.y;
    int bi = hy >> 3, h = hy & 7;
    int t0 = blockIdx.x << 6;
    int tid = threadIdx.x;
    int tx = tid & 15, ty = tid >> 4;

    const float* qcb = Qc + (long)bi * qc_bs + (long)(h * 64) * Lq + t0;
    const float* qpb = Qp + (long)bi * qp_bs + (long)(h * 64) * Lq + t0;
    for (int idx = tid; idx < 8192; idx += 256) {
        int c = idx >> 6, t = idx & 63;
        float v = (c < 64) ? qcb[(long)c * Lq + t] : qpb[(long)(c - 64) * Lq + t];
        Qs[idx] = v * sc2;
    }

    float m_[4], l_[4], acc[4][4];
    #pragma unroll
    for (int i = 0; i < 4; i++) {
        m_[i] = -1e30f; l_[i] = 0.f;
        #pragma unroll
        for (int j = 0; j < 4; j++) acc[i][j] = 0.f;
    }

    const float* kcb = Kc + (long)bi * kc_bs + (long)(h * 64) * Ls;
    const float* kpb = Kp + (long)bi * kp_bs + (long)(h * 64) * Ls;
    const float* vb  = V  + (long)bi * v_bs  + (long)(h * 64) * Ls;

    int nT = Ls >> 6;
    for (int it = 0; it < nT; it++) {
        int s0 = it << 6;
        for (int idx = tid; idx < 8192; idx += 256) {
            int c = idx >> 6, s = idx & 63;
            Ks[idx] = (c < 64) ? kcb[(long)c * Ls + s0 + s]
                               : kpb[(long)(c - 64) * Ls + s0 + s];
        }
        for (int idx = tid; idx < 4096; idx += 256) {
            int c = idx >> 6, s = idx & 63;
            Vs[s * VS_STRIDE + c] = vb[(long)c * Ls + s0 + s];
        }
        __syncthreads();

        float S[4][4];
        #pragma unroll
        for (int i = 0; i < 4; i++)
            #pragma unroll
            for (int j = 0; j < 4; j++) S[i][j] = 0.f;

        #pragma unroll 8
        for (int c = 0; c < 128; c++) {
            float qv[4], kv4[4];
            *(float4*)qv  = *(const float4*)&Qs[c * 64 + ty * 4];
            *(float4*)kv4 = *(const float4*)&Ks[c * 64 + tx * 4];
            #pragma unroll
            for (int i = 0; i < 4; i++)
                #pragma unroll
                for (int j = 0; j < 4; j++)
                    S[i][j] += qv[i] * kv4[j];
        }

        #pragma unroll
        for (int i = 0; i < 4; i++) {
            float rmax = fmaxf(fmaxf(S[i][0], S[i][1]), fmaxf(S[i][2], S[i][3]));
            rmax = fmaxf(rmax, __shfl_xor_sync(0xffffffffu, rmax, 1));
            rmax = fmaxf(rmax, __shfl_xor_sync(0xffffffffu, rmax, 2));
            rmax = fmaxf(rmax, __shfl_xor_sync(0xffffffffu, rmax, 4));
            rmax = fmaxf(rmax, __shfl_xor_sync(0xffffffffu, rmax, 8));
            float mn = fmaxf(m_[i], rmax);
            float corr = __expf(m_[i] - mn);
            float rs = 0.f;
            #pragma unroll
            for (int j = 0; j < 4; j++) {
                S[i][j] = __expf(S[i][j] - mn);
                rs += S[i][j];
            }
            rs += __shfl_xor_sync(0xffffffffu, rs, 1);
            rs += __shfl_xor_sync(0xffffffffu, rs, 2);
            rs += __shfl_xor_sync(0xffffffffu, rs, 4);
            rs += __shfl_xor_sync(0xffffffffu, rs, 8);
            l_[i] = l_[i] * corr + rs;
            m_[i] = mn;
            #pragma unroll
            for (int j = 0; j < 4; j++) acc[i][j] *= corr;
            *(float4*)&Ps[(ty * 4 + i) * 64 + tx * 4] = *(float4*)&S[i][0];
        }
        __syncthreads();

        #pragma unroll 8
        for (int s = 0; s < 64; s++) {
            float vv[4];
            *(float4*)vv = *(const float4*)&Vs[s * VS_STRIDE + tx * 4];
            #pragma unroll
            for (int i = 0; i < 4; i++) {
                float p = Ps[(ty * 4 + i) * 64 + s];
                #pragma unroll
                for (int j = 0; j < 4; j++) acc[i][j] += p * vv[j];
            }
        }
        __syncthreads();
    }

    // transpose through smem for coalesced global stores: Os[c][t]
    #pragma unroll
    for (int i = 0; i < 4; i++) {
        float invl = 1.f / l_[i];
        #pragma unroll
        for (int j = 0; j < 4; j++)
            Ps[(tx * 4 + j) * OS_STRIDE + ty * 4 + i] = acc[i][j] * invl;
    }
    __syncthreads();
    float* ob = O + (long)bi * o_bs + (long)(h * 64) * Lq + t0;
    for (int idx = tid; idx < 4096; idx += 256) {
        int c = idx >> 6, t = idx & 63;
        ob[(long)c * Lq + t] = Ps[c * OS_STRIDE + t];
    }
}

// ---------------- launch ----------------
extern "C" void kernel_launch(void* const* d_in, const int* in_sizes, int n_in,
                              void* d_out, int out_size)
{
    const float* x           = (const float*)d_in[0];
    const float* xf_out      = (const float*)d_in[1];
    const float* obj_contour = (const float*)d_in[2];
    const float* obj_desc    = (const float*)d_in[3];
    const float* ipce        = (const float*)d_in[4];
    const float* gn_qkv_g    = (const float*)d_in[5];
    const float* gn_qkv_b    = (const float*)d_in[6];
    const float* W_self_qkv  = (const float*)d_in[7];
    const float* b_self_qkv  = (const float*)d_in[8];
    const float* W_cross_q   = (const float*)d_in[9];
    const float* b_cross_q   = (const float*)d_in[10];
    const float* W_content   = (const float*)d_in[11];
    const float* b_content   = (const float*)d_in[12];
    const float* W_pos       = (const float*)d_in[13];
    const float* b_pos       = (const float*)d_in[14];
    const float* gn_desc_g   = (const float*)d_in[15];
    const float* gn_desc_b   = (const float*)d_in[16];
    const float* gn_cpos_g   = (const float*)d_in[17];
    const float* gn_cpos_b   = (const float*)d_in[18];
    const float* gn_ipos_g   = (const float*)d_in[19];
    const float* gn_ipos_b   = (const float*)d_in[20];
    const float* W_self_out  = (const float*)d_in[21];
    const float* b_self_out  = (const float*)d_in[22];
    const float* W_cross_out = (const float*)d_in[23];
    const float* b_cross_out = (const float*)d_in[24];
    float* out = (float*)d_out;

    float *gn1, *qkv, *ipos, *attn, *xf2, *cpos, *content, *kv;
    cudaGetSymbolAddress((void**)&gn1,     g_gn1);
    cudaGetSymbolAddress((void**)&qkv,     g_qkv);
    cudaGetSymbolAddress((void**)&ipos,    g_ipos);
    cudaGetSymbolAddress((void**)&attn,    g_attnbuf);
    cudaGetSymbolAddress((void**)&xf2,     g_xf2);
    cudaGetSymbolAddress((void**)&cpos,    g_cpos);
    cudaGetSymbolAddress((void**)&content, g_content);
    cudaGetSymbolAddress((void**)&kv,      g_kv);
    float* cq = qkv;  // reuse: self qkv dead after steps 5/6

    cudaFuncSetAttribute(attn_kernel, cudaFuncAttributeMaxDynamicSharedMemorySize,
                         ATTN_SMEM_BYTES);

    const float sc2 = 0.08838834764831845f;  // 128^-0.5
    const float eps = 1e-5f;

    // 1. gn1 = GN(xf)
    gn_kernel<<<BB * 32, 256>>>(x, gn1, gn_qkv_g, gn_qkv_b, nullptr, 512, 16, 1024, eps);
    // 2. qkv = W_self_qkv @ gn1 + b
    sgemm128<<<dim3(8, 12, BB), 256>>>(W_self_qkv, gn1, b_self_qkv, nullptr, qkv,
                                       1536, 1024, 512, 512L * 1024, 1536L * 1024, 0);
    // 3. ipos = W_pos @ ipce + b_pos
    sgemm128<<<dim3(8, 4, BB), 256>>>(W_pos, ipce, b_pos, nullptr, ipos,
                                      512, 1024, 512, 512L * 1024, 512L * 1024, 0);
    // 4. ipos = GN(ipos) in-place
    gn_kernel<<<BB * 32, 256>>>(ipos, ipos, gn_ipos_g, gn_ipos_b, nullptr, 512, 16, 1024, eps);
    // 5. self attention
    attn_kernel<<<dim3(16, 64), 256, ATTN_SMEM_BYTES>>>(
        qkv, 1536L * 1024, ipos, 512L * 1024,
        qkv + 512L * 1024, 1536L * 1024, ipos, 512L * 1024,
        qkv + 1024L * 1024, 1536L * 1024,
        attn, 512L * 1024, 1024, 1024, sc2);
    // 6. xf2 = x + W_self_out @ attn + b
    sgemm128<<<dim3(8, 4, BB), 256>>>(W_self_out, attn, b_self_out, x, xf2,
                                      512, 1024, 512, 512L * 1024, 512L * 1024, 512L * 1024);
    // 7. gn1 = GN(xf2)
    gn_kernel<<<BB * 32, 256>>>(xf2, gn1, gn_qkv_g, gn_qkv_b, nullptr, 512, 16, 1024, eps);
    // 8. cq = W_cross_q @ gn1 + b   (into reused qkv buffer)
    sgemm128<<<dim3(8, 4, BB), 256>>>(W_cross_q, gn1, b_cross_q, nullptr, cq,
                                      512, 1024, 512, 512L * 1024, 512L * 1024, 0);
    // 9. cpos = W_pos @ obj_contour + b_pos
    sgemm128<<<dim3(1, 4, BB), 256>>>(W_pos, obj_contour, b_pos, nullptr, cpos,
                                      512, 64, 512, 512L * 64, 512L * 64, 0);
    // 10. cpos = GN(cpos)
    gn_kernel<<<BB * 32, 256>>>(cpos, cpos, gn_cpos_g, gn_cpos_b, nullptr, 512, 16, 64, eps);
    // 11. content = (xf_out + GN(obj_desc)) / 2
    gn_kernel<<<BB * 32, 256>>>(obj_desc, content, gn_desc_g, gn_desc_b, xf_out, 512, 16, 64, eps);
    // 12. kv = W_content @ content + b
    sgemm128<<<dim3(1, 8, BB), 256>>>(W_content, content, b_content, nullptr, kv,
                                      1024, 64, 512, 512L * 64, 1024L * 64, 0);
    // 13. cross attention
    attn_kernel<<<dim3(16, 64), 256, ATTN_SMEM_BYTES>>>(
        cq, 512L * 1024, ipos, 512L * 1024,
        kv, 1024L * 64, cpos, 512L * 64,
        kv + 512L * 64, 1024L * 64,
        attn, 512L * 1024, 1024, 64, sc2);
    // 14. out = xf2 + W_cross_out @ attn + b
    sgemm128<<<dim3(8, 4, BB), 256>>>(W_cross_out, attn, b_cross_out, xf2, out,
                                      512, 1024, 512, 512L * 1024, 512L * 1024, 512L * 1024);
}

// round 4
// speedup vs baseline: 1.0423x; 1.0423x over previous
#include <cuda_runtime.h>
#include <cuda_bf16.h>

#define BB 8
#define CCH 512
#define LL1 1024
#define LL2 64
#define NHH 8

// ---------------- scratch (no allocations allowed) ----------------
__device__ float g_gn1[BB*CCH*LL1];        // 16 MB
__device__ float g_qkv[BB*3*CCH*LL1];      // 48 MB (self qkv; later cross q)
__device__ float g_ipos[BB*CCH*LL1];       // 16 MB
__device__ float g_attnbuf[BB*CCH*LL1];    // 16 MB
__device__ float g_xf2[BB*CCH*LL1];        // 16 MB
__device__ float g_cpos[BB*CCH*LL2];
__device__ float g_content[BB*CCH*LL2];
__device__ float g_kv[BB*2*CCH*LL2];

// ---------------- GroupNorm ----------------
__global__ __launch_bounds__(256) void gn_kernel(
    const float* __restrict__ in, float* __restrict__ out,
    const float* __restrict__ g, const float* __restrict__ b,
    const float* __restrict__ post,
    int C, int Cg, int L, float eps)
{
    int G = C / Cg;
    int bi = blockIdx.x / G, gi = blockIdx.x % G;
    long base = (long)bi * C * L + (long)gi * Cg * L;
    int n = Cg * L;
    float s = 0.f, s2 = 0.f;
    for (int i = threadIdx.x; i < n; i += 256) {
        float v = in[base + i];
        s += v; s2 += v * v;
    }
    __shared__ float r1[256], r2[256];
    r1[threadIdx.x] = s; r2[threadIdx.x] = s2;
    __syncthreads();
    for (int off = 128; off > 0; off >>= 1) {
        if (threadIdx.x < off) {
            r1[threadIdx.x] += r1[threadIdx.x + off];
            r2[threadIdx.x] += r2[threadIdx.x + off];
        }
        __syncthreads();
    }
    float mean = r1[0] / n;
    float var  = r2[0] / n - mean * mean;
    float inv  = rsqrtf(var + eps);
    for (int i = threadIdx.x; i < n; i += 256) {
        int c = gi * Cg + i / L;
        float v = (in[base + i] - mean) * inv * g[c] + b[c];
        if (post) v = 0.5f * (post[base + i] + v);
        out[base + i] = v;
    }
}

// ---------------- batched SGEMM, double-buffered smem ----------------
// Y[b] = A(MxK) @ X[b](KxN) + bias (+ res). 128x128 tile, BK=8, 256 thr, 8x8/thread.
__global__ __launch_bounds__(256) void sgemm128(
    const float* __restrict__ A, const float* __restrict__ Bx,
    const float* __restrict__ bias, const float* __restrict__ res,
    float* __restrict__ Y,
    int M, int N, int K, long x_bs, long y_bs, long r_bs)
{
    __shared__ float As[2][8][128];
    __shared__ float Bs[2][8][128];
    int bz = blockIdx.z;
    const float* X = Bx + (long)bz * x_bs;
    int m0 = blockIdx.y * 128, n0 = blockIdx.x * 128;
    int tid = threadIdx.x;
    int tx = tid & 15, ty = tid >> 4;
    float acc[8][8];
    #pragma unroll
    for (int i = 0; i < 8; i++)
        #pragma unroll
        for (int j = 0; j < 8; j++) acc[i][j] = 0.f;

    int aRow  = tid >> 1;       // 0..127
    int aColB = (tid & 1) * 4;  // 0 or 4
    int bRow  = tid >> 5;       // 0..7
    int bColB = (tid & 31) * 4; // 0..124
    int am = m0 + aRow;
    int bn = n0 + bColB;

    // prologue: stage 0
    {
        float4 av = make_float4(0.f, 0.f, 0.f, 0.f);
        if (am < M) av = *(const float4*)(A + (long)am * K + aColB);
        As[0][aColB + 0][aRow] = av.x;
        As[0][aColB + 1][aRow] = av.y;
        As[0][aColB + 2][aRow] = av.z;
        As[0][aColB + 3][aRow] = av.w;
        float4 bv = make_float4(0.f, 0.f, 0.f, 0.f);
        if (bn < N) bv = *(const float4*)(X + (long)bRow * N + bn);
        *(float4*)&Bs[0][bRow][bColB] = bv;
    }
    __syncthreads();

    int cur = 0;
    for (int k0 = 0; k0 < K; k0 += 8) {
        bool has = (k0 + 8) < K;
        float4 avn = make_float4(0.f, 0.f, 0.f, 0.f);
        float4 bvn = make_float4(0.f, 0.f, 0.f, 0.f);
        if (has) {
            if (am < M) avn = *(const float4*)(A + (long)am * K + k0 + 8 + aColB);
            if (bn < N) bvn = *(const float4*)(X + (long)(k0 + 8 + bRow) * N + bn);
        }
        #pragma unroll
        for (int kk = 0; kk < 8; kk++) {
            float ra[8], rb[8];
            *(float4*)&ra[0] = *(const float4*)&As[cur][kk][ty * 4];
            *(float4*)&ra[4] = *(const float4*)&As[cur][kk][64 + ty * 4];
            *(float4*)&rb[0] = *(const float4*)&Bs[cur][kk][tx * 4];
            *(float4*)&rb[4] = *(const float4*)&Bs[cur][kk][64 + tx * 4];
            #pragma unroll
            for (int i = 0; i < 8; i++)
                #pragma unroll
                for (int j = 0; j < 8; j++)
                    acc[i][j] += ra[i] * rb[j];
        }
        if (has) {
            int nxt = cur ^ 1;
            As[nxt][aColB + 0][aRow] = avn.x;
            As[nxt][aColB + 1][aRow] = avn.y;
            As[nxt][aColB + 2][aRow] = avn.z;
            As[nxt][aColB + 3][aRow] = avn.w;
            *(float4*)&Bs[nxt][bRow][bColB] = bvn;
        }
        __syncthreads();
        cur ^= 1;
    }
    #pragma unroll
    for (int i = 0; i < 8; i++) {
        int m = m0 + ((i < 4) ? ty * 4 + i : 64 + ty * 4 + (i - 4));
        if (m >= M) continue;
        float bvv = bias[m];
        #pragma unroll
        for (int j = 0; j < 8; j++) {
            int n = n0 + ((j < 4) ? tx * 4 + j : 64 + tx * 4 + (j - 4));
            if (n >= N) continue;
            float v = acc[i][j] + bvv;
            if (res) v += res[(long)bz * r_bs + (long)m * N + n];
            Y[(long)bz * y_bs + (long)m * N + n] = v;
        }
    }
}

// ---------------- flash-style attention, 128q x 64s tiles, 8x4 per thread ----------------
// smem (floats): Qs[128c][128t] @0 (16384), Ks[128c][64s] @16384 (8192),
//                Vs[64s][64c] stride 68 @24576 (4352), Ps[128t][64s] stride 68 @28928 (8704).
// Ps reused as Os[64c][128t] stride 129 for coalesced output.
#define PS_STRIDE 68
#define VS_STRIDE 68
#define OS_STRIDE 129
#define ATTN_SMEM_FLOATS (16384 + 8192 + 64*VS_STRIDE + 128*PS_STRIDE)
#define ATTN_SMEM_BYTES (ATTN_SMEM_FLOATS * 4)

__global__ __launch_bounds__(256, 1) void attn_kernel(
    const float* __restrict__ Qc, long qc_bs,
    const float* __restrict__ Qp, long qp_bs,
    const float* __restrict__ Kc, long kc_bs,
    const float* __restrict__ Kp, long kp_bs,
    const float* __restrict__ V,  long v_bs,
    float* __restrict__ O, long o_bs,
    int Lq, int Ls, float sc2)
{
    extern __shared__ float sm[];
    float* Qs = sm;                    // 128 x 128
    float* Ks = sm + 16384;            // 128 x 64
    float* Vs = sm + 24576;            // 64 x VS_STRIDE
    float* Ps = sm + 24576 + 64 * VS_STRIDE;  // 128 x PS_STRIDE (also Os)

    int hy = blockIdx.y;
    int bi = hy >> 3, h = hy & 7;
    int t0 = blockIdx.x << 7;          // 128-query tile
    int tid = threadIdx.x;
    int tx = tid & 15, ty = tid >> 4;

    // load Q (content||pos), pre-scaled; float4 over t
    const float* qcb = Qc + (long)bi * qc_bs + (long)(h * 64) * Lq + t0;
    const float* qpb = Qp + (long)bi * qp_bs + (long)(h * 64) * Lq + t0;
    for (int idx = tid; idx < 4096; idx += 256) {
        int c = idx >> 5, t4 = (idx & 31) << 2;
        float4 v = (c < 64) ? *(const float4*)(qcb + (long)c * Lq + t4)
                            : *(const float4*)(qpb + (long)(c - 64) * Lq + t4);
        v.x *= sc2; v.y *= sc2; v.z *= sc2; v.w *= sc2;
        *(float4*)&Qs[c * 128 + t4] = v;
    }

    float m_[8], l_[8], acc[8][4];
    #pragma unroll
    for (int i = 0; i < 8; i++) {
        m_[i] = -1e30f; l_[i] = 0.f;
        #pragma unroll
        for (int j = 0; j < 4; j++) acc[i][j] = 0.f;
    }

    const float* kcb = Kc + (long)bi * kc_bs + (long)(h * 64) * Ls;
    const float* kpb = Kp + (long)bi * kp_bs + (long)(h * 64) * Ls;
    const float* vb  = V  + (long)bi * v_bs  + (long)(h * 64) * Ls;

    int nT = Ls >> 6;
    for (int it = 0; it < nT; it++) {
        int s0 = it << 6;
        // K tile: float4 over s
        for (int idx = tid; idx < 2048; idx += 256) {
            int c = idx >> 4, s4 = (idx & 15) << 2;
            float4 v = (c < 64) ? *(const float4*)(kcb + (long)c * Ls + s0 + s4)
                                : *(const float4*)(kpb + (long)(c - 64) * Ls + s0 + s4);
            *(float4*)&Ks[c * 64 + s4] = v;
        }
        // V tile transposed: Vs[s][c]
        for (int idx = tid; idx < 4096; idx += 256) {
            int c = idx >> 6, s = idx & 63;
            Vs[s * VS_STRIDE + c] = vb[(long)c * Ls + s0 + s];
        }
        __syncthreads();

        // scores: S[8 q][4 s]
        float S[8][4];
        #pragma unroll
        for (int i = 0; i < 8; i++)
            #pragma unroll
            for (int j = 0; j < 4; j++) S[i][j] = 0.f;

        #pragma unroll 4
        for (int c = 0; c < 128; c++) {
            float qv[8], kv4[4];
            *(float4*)&qv[0] = *(const float4*)&Qs[c * 128 + ty * 4];
            *(float4*)&qv[4] = *(const float4*)&Qs[c * 128 + 64 + ty * 4];
            *(float4*)&kv4[0] = *(const float4*)&Ks[c * 64 + tx * 4];
            #pragma unroll
            for (int i = 0; i < 8; i++)
                #pragma unroll
                for (int j = 0; j < 4; j++)
                    S[i][j] += qv[i] * kv4[j];
        }

        // online softmax (reduce over s: 4 local + 16 lanes of tx)
        #pragma unroll
        for (int i = 0; i < 8; i++) {
            float rmax = fmaxf(fmaxf(S[i][0], S[i][1]), fmaxf(S[i][2], S[i][3]));
            rmax = fmaxf(rmax, __shfl_xor_sync(0xffffffffu, rmax, 1));
            rmax = fmaxf(rmax, __shfl_xor_sync(0xffffffffu, rmax, 2));
            rmax = fmaxf(rmax, __shfl_xor_sync(0xffffffffu, rmax, 4));
            rmax = fmaxf(rmax, __shfl_xor_sync(0xffffffffu, rmax, 8));
            float mn = fmaxf(m_[i], rmax);
            float corr = __expf(m_[i] - mn);
            float rs = 0.f;
            #pragma unroll
            for (int j = 0; j < 4; j++) {
                S[i][j] = __expf(S[i][j] - mn);
                rs += S[i][j];
            }
            rs += __shfl_xor_sync(0xffffffffu, rs, 1);
            rs += __shfl_xor_sync(0xffffffffu, rs, 2);
            rs += __shfl_xor_sync(0xffffffffu, rs, 4);
            rs += __shfl_xor_sync(0xffffffffu, rs, 8);
            l_[i] = l_[i] * corr + rs;
            m_[i] = mn;
            #pragma unroll
            for (int j = 0; j < 4; j++) acc[i][j] *= corr;
            int q = (i < 4) ? ty * 4 + i : 64 + ty * 4 + (i - 4);
            *(float4*)&Ps[q * PS_STRIDE + tx * 4] = *(float4*)&S[i][0];
        }
        __syncthreads();

        // PV: s-groups of 4, fully vectorized smem reads
        #pragma unroll 2
        for (int sg = 0; sg < 16; sg++) {
            float vv[4][4];
            #pragma unroll
            for (int s = 0; s < 4; s++)
                *(float4*)&vv[s][0] = *(const float4*)&Vs[(sg * 4 + s) * VS_STRIDE + tx * 4];
            #pragma unroll
            for (int i = 0; i < 8; i++) {
                int q = (i < 4) ? ty * 4 + i : 64 + ty * 4 + (i - 4);
                float p[4];
                *(float4*)&p[0] = *(const float4*)&Ps[q * PS_STRIDE + sg * 4];
                #pragma unroll
                for (int s = 0; s < 4; s++)
                    #pragma unroll
                    for (int j = 0; j < 4; j++)
                        acc[i][j] += p[s] * vv[s][j];
            }
        }
        __syncthreads();
    }

    // write O via smem transpose: Os[c][t] stride 129
    float* Os = Ps;
    #pragma unroll
    for (int i = 0; i < 8; i++) {
        int q = (i < 4) ? ty * 4 + i : 64 + ty * 4 + (i - 4);
        float invl = 1.f / l_[i];
        #pragma unroll
        for (int j = 0; j < 4; j++)
            Os[(tx * 4 + j) * OS_STRIDE + q] = acc[i][j] * invl;
    }
    __syncthreads();
    float* ob = O + (long)bi * o_bs + (long)(h * 64) * Lq + t0;
    for (int idx = tid; idx < 8192; idx += 256) {
        int c = idx >> 7, t = idx & 127;
        ob[(long)c * Lq + t] = Os[c * OS_STRIDE + t];
    }
}

// ---------------- launch ----------------
extern "C" void kernel_launch(void* const* d_in, const int* in_sizes, int n_in,
                              void* d_out, int out_size)
{
    const float* x           = (const float*)d_in[0];
    const float* xf_out      = (const float*)d_in[1];
    const float* obj_contour = (const float*)d_in[2];
    const float* obj_desc    = (const float*)d_in[3];
    const float* ipce        = (const float*)d_in[4];
    const float* gn_qkv_g    = (const float*)d_in[5];
    const float* gn_qkv_b    = (const float*)d_in[6];
    const float* W_self_qkv  = (const float*)d_in[7];
    const float* b_self_qkv  = (const float*)d_in[8];
    const float* W_cross_q   = (const float*)d_in[9];
    const float* b_cross_q   = (const float*)d_in[10];
    const float* W_content   = (const float*)d_in[11];
    const float* b_content   = (const float*)d_in[12];
    const float* W_pos       = (const float*)d_in[13];
    const float* b_pos       = (const float*)d_in[14];
    const float* gn_desc_g   = (const float*)d_in[15];
    const float* gn_desc_b   = (const float*)d_in[16];
    const float* gn_cpos_g   = (const float*)d_in[17];
    const float* gn_cpos_b   = (const float*)d_in[18];
    const float* gn_ipos_g   = (const float*)d_in[19];
    const float* gn_ipos_b   = (const float*)d_in[20];
    const float* W_self_out  = (const float*)d_in[21];
    const float* b_self_out  = (const float*)d_in[22];
    const float* W_cross_out = (const float*)d_in[23];
    const float* b_cross_out = (const float*)d_in[24];
    float* out = (float*)d_out;

    float *gn1, *qkv, *ipos, *attn, *xf2, *cpos, *content, *kv;
    cudaGetSymbolAddress((void**)&gn1,     g_gn1);
    cudaGetSymbolAddress((void**)&qkv,     g_qkv);
    cudaGetSymbolAddress((void**)&ipos,    g_ipos);
    cudaGetSymbolAddress((void**)&attn,    g_attnbuf);
    cudaGetSymbolAddress((void**)&xf2,     g_xf2);
    cudaGetSymbolAddress((void**)&cpos,    g_cpos);
    cudaGetSymbolAddress((void**)&content, g_content);
    cudaGetSymbolAddress((void**)&kv,      g_kv);
    float* cq = qkv;  // reuse: self qkv dead after steps 5/6

    cudaFuncSetAttribute(attn_kernel, cudaFuncAttributeMaxDynamicSharedMemorySize,
                         ATTN_SMEM_BYTES);

    const float sc2 = 0.08838834764831845f;  // 128^-0.5
    const float eps = 1e-5f;

    // 1. gn1 = GN(xf)
    gn_kernel<<<BB * 32, 256>>>(x, gn1, gn_qkv_g, gn_qkv_b, nullptr, 512, 16, 1024, eps);
    // 2. qkv = W_self_qkv @ gn1 + b
    sgemm128<<<dim3(8, 12, BB), 256>>>(W_self_qkv, gn1, b_self_qkv, nullptr, qkv,
                                       1536, 1024, 512, 512L * 1024, 1536L * 1024, 0);
    // 3. ipos = W_pos @ ipce + b_pos
    sgemm128<<<dim3(8, 4, BB), 256>>>(W_pos, ipce, b_pos, nullptr, ipos,
                                      512, 1024, 512, 512L * 1024, 512L * 1024, 0);
    // 4. ipos = GN(ipos) in-place
    gn_kernel<<<BB * 32, 256>>>(ipos, ipos, gn_ipos_g, gn_ipos_b, nullptr, 512, 16, 1024, eps);
    // 5. self attention (8 q-tiles x 64 bh)
    attn_kernel<<<dim3(8, 64), 256, ATTN_SMEM_BYTES>>>(
        qkv, 1536L * 1024, ipos, 512L * 1024,
        qkv + 512L * 1024, 1536L * 1024, ipos, 512L * 1024,
        qkv + 1024L * 1024, 1536L * 1024,
        attn, 512L * 1024, 1024, 1024, sc2);
    // 6. xf2 = x + W_self_out @ attn + b
    sgemm128<<<dim3(8, 4, BB), 256>>>(W_self_out, attn, b_self_out, x, xf2,
                                      512, 1024, 512, 512L * 1024, 512L * 1024, 512L * 1024);
    // 7. gn1 = GN(xf2)
    gn_kernel<<<BB * 32, 256>>>(xf2, gn1, gn_qkv_g, gn_qkv_b, nullptr, 512, 16, 1024, eps);
    // 8. cq = W_cross_q @ gn1 + b   (into reused qkv buffer)
    sgemm128<<<dim3(8, 4, BB), 256>>>(W_cross_q, gn1, b_cross_q, nullptr, cq,
                                      512, 1024, 512, 512L * 1024, 512L * 1024, 0);
    // 9. cpos = W_pos @ obj_contour + b_pos
    sgemm128<<<dim3(1, 4, BB), 256>>>(W_pos, obj_contour, b_pos, nullptr, cpos,
                                      512, 64, 512, 512L * 64, 512L * 64, 0);
    // 10. cpos = GN(cpos)
    gn_kernel<<<BB * 32, 256>>>(cpos, cpos, gn_cpos_g, gn_cpos_b, nullptr, 512, 16, 64, eps);
    // 11. content = (xf_out + GN(obj_desc)) / 2
    gn_kernel<<<BB * 32, 256>>>(obj_desc, content, gn_desc_g, gn_desc_b, xf_out, 512, 16, 64, eps);
    // 12. kv = W_content @ content + b
    sgemm128<<<dim3(1, 8, BB), 256>>>(W_content, content, b_content, nullptr, kv,
                                      1024, 64, 512, 512L * 64, 1024L * 64, 0);
    // 13. cross attention (Ls = 64)
    attn_kernel<<<dim3(8, 64), 256, ATTN_SMEM_BYTES>>>(
        cq, 512L * 1024, ipos, 512L * 1024,
        kv, 1024L * 64, cpos, 512L * 64,
        kv + 512L * 64, 1024L * 64,
        attn, 512L * 1024, 1024, 64, sc2);
    // 14. out = xf2 + W_cross_out @ attn + b
    sgemm128<<<dim3(8, 4, BB), 256>>>(W_cross_out, attn, b_cross_out, xf2, out,
                                      512, 1024, 512, 512L * 1024, 512L * 1024, 512L * 1024);
}

// round 5
// speedup vs baseline: 2.4541x; 2.3546x over previous
#include <cuda_runtime.h>
#include <cuda_bf16.h>
#include <cstdint>

#define BB 8
#define CCH 512
#define LL1 1024
#define LL2 64

// ---------------- scratch (no allocations allowed) ----------------
__device__ float g_gn1[BB*CCH*LL1];
__device__ float g_qkv[BB*3*CCH*LL1];
__device__ float g_ipos[BB*CCH*LL1];
__device__ float g_attnbuf[BB*CCH*LL1];
__device__ float g_xf2[BB*CCH*LL1];
__device__ float g_cpos[BB*CCH*LL2];
__device__ float g_content[BB*CCH*LL2];
__device__ float g_kv[BB*2*CCH*LL2];

// ---------------- tf32 mma helper ----------------
__device__ __forceinline__ void mma_tf32(float c[4], const uint32_t a[4],
                                         uint32_t b0, uint32_t b1) {
    asm volatile(
        "mma.sync.aligned.m16n8k8.row.col.f32.tf32.tf32.f32 "
        "{%0,%1,%2,%3}, {%4,%5,%6,%7}, {%8,%9}, {%0,%1,%2,%3};\n"
        : "+f"(c[0]), "+f"(c[1]), "+f"(c[2]), "+f"(c[3])
        : "r"(a[0]), "r"(a[1]), "r"(a[2]), "r"(a[3]), "r"(b0), "r"(b1));
}

// ---------------- GroupNorm ----------------
__global__ __launch_bounds__(256) void gn_kernel(
    const float* __restrict__ in, float* __restrict__ out,
    const float* __restrict__ g, const float* __restrict__ b,
    const float* __restrict__ post,
    int C, int Cg, int L, float eps)
{
    int G = C / Cg;
    int bi = blockIdx.x / G, gi = blockIdx.x % G;
    long base = (long)bi * C * L + (long)gi * Cg * L;
    int n = Cg * L;
    float s = 0.f, s2 = 0.f;
    for (int i = threadIdx.x; i < n; i += 256) {
        float v = in[base + i];
        s += v; s2 += v * v;
    }
    __shared__ float r1[256], r2[256];
    r1[threadIdx.x] = s; r2[threadIdx.x] = s2;
    __syncthreads();
    for (int off = 128; off > 0; off >>= 1) {
        if (threadIdx.x < off) {
            r1[threadIdx.x] += r1[threadIdx.x + off];
            r2[threadIdx.x] += r2[threadIdx.x + off];
        }
        __syncthreads();
    }
    float mean = r1[0] / n;
    float var  = r2[0] / n - mean * mean;
    float inv  = rsqrtf(var + eps);
    for (int i = threadIdx.x; i < n; i += 256) {
        int c = gi * Cg + i / L;
        float v = (in[base + i] - mean) * inv * g[c] + b[c];
        if (post) v = 0.5f * (post[base + i] + v);
        out[base + i] = v;
    }
}

// ---------------- tensor-core GEMM: Y[b] = A(MxK) @ X[b](KxN) + bias (+res) ----------------
// 128x128 block tile, K-step 16, double buffered. 8 warps in 4x2, warp tile 32x64.
#define APAD 20
#define BPAD 136

__global__ __launch_bounds__(256) void gemm_tc(
    const float* __restrict__ A, const float* __restrict__ Bx,
    const float* __restrict__ bias, const float* __restrict__ res,
    float* __restrict__ Y,
    int M, int N, int K, long x_bs, long y_bs, long r_bs)
{
    __shared__ float As[2][128 * APAD];
    __shared__ float Bs[2][16 * BPAD];
    int bz = blockIdx.z;
    const float* X = Bx + (long)bz * x_bs;
    int m0 = blockIdx.y * 128, n0 = blockIdx.x * 128;
    int tid = threadIdx.x;
    int lane = tid & 31, warp = tid >> 5;
    int gid = lane >> 2, tg = lane & 3;
    int wm = warp >> 1, wn = warp & 1;

    float C[2][8][4];
    #pragma unroll
    for (int i = 0; i < 2; i++)
        #pragma unroll
        for (int j = 0; j < 8; j++)
            #pragma unroll
            for (int k = 0; k < 4; k++) C[i][j][k] = 0.f;

    // load mapping: A 512 float4 (m=idx>>2, p=idx&3), B 512 float4 (k=idx>>5, c=idx&31)
    float4 av[2], bv[2];
    #pragma unroll
    for (int u = 0; u < 2; u++) {
        int ia = tid + u * 256;
        av[u] = *(const float4*)(A + (long)(m0 + (ia >> 2)) * K + 4 * (ia & 3));
        int ib = tid + u * 256;
        int bn = 4 * (ib & 31);
        bv[u] = (bn < N) ? *(const float4*)(X + (long)(ib >> 5) * N + n0 + bn)
                         : make_float4(0.f, 0.f, 0.f, 0.f);
    }
    #pragma unroll
    for (int u = 0; u < 2; u++) {
        int ia = tid + u * 256;
        *(float4*)&As[0][(ia >> 2) * APAD + 4 * (ia & 3)] = av[u];
        int ib = tid + u * 256;
        *(float4*)&Bs[0][(ib >> 5) * BPAD + 4 * (ib & 31)] = bv[u];
    }
    __syncthreads();

    int nsteps = K >> 4;
    for (int s = 0; s < nsteps; s++) {
        int cur = s & 1;
        if (s + 1 < nsteps) {
            int k0 = (s + 1) * 16;
            #pragma unroll
            for (int u = 0; u < 2; u++) {
                int ia = tid + u * 256;
                av[u] = *(const float4*)(A + (long)(m0 + (ia >> 2)) * K + k0 + 4 * (ia & 3));
                int ib = tid + u * 256;
                int bn = 4 * (ib & 31);
                bv[u] = (bn < N) ? *(const float4*)(X + (long)(k0 + (ib >> 5)) * N + n0 + bn)
                                 : make_float4(0.f, 0.f, 0.f, 0.f);
            }
        }
        const float* As_ = As[cur];
        const float* Bs_ = Bs[cur];
        #pragma unroll
        for (int kf = 0; kf < 2; kf++) {
            int kk = kf * 8;
            uint32_t a[2][4];
            #pragma unroll
            for (int mf = 0; mf < 2; mf++) {
                int mr = wm * 32 + mf * 16;
                a[mf][0] = __float_as_uint(As_[(mr + gid) * APAD + kk + tg]);
                a[mf][1] = __float_as_uint(As_[(mr + gid + 8) * APAD + kk + tg]);
                a[mf][2] = __float_as_uint(As_[(mr + gid) * APAD + kk + tg + 4]);
                a[mf][3] = __float_as_uint(As_[(mr + gid + 8) * APAD + kk + tg + 4]);
            }
            #pragma unroll
            for (int nf = 0; nf < 8; nf++) {
                int nc = wn * 64 + nf * 8;
                uint32_t b0 = __float_as_uint(Bs_[(kk + tg) * BPAD + nc + gid]);
                uint32_t b1 = __float_as_uint(Bs_[(kk + tg + 4) * BPAD + nc + gid]);
                mma_tf32(C[0][nf], a[0], b0, b1);
                mma_tf32(C[1][nf], a[1], b0, b1);
            }
        }
        if (s + 1 < nsteps) {
            int nxt = cur ^ 1;
            #pragma unroll
            for (int u = 0; u < 2; u++) {
                int ia = tid + u * 256;
                *(float4*)&As[nxt][(ia >> 2) * APAD + 4 * (ia & 3)] = av[u];
                int ib = tid + u * 256;
                *(float4*)&Bs[nxt][(ib >> 5) * BPAD + 4 * (ib & 31)] = bv[u];
            }
        }
        __syncthreads();
    }

    // epilogue
    #pragma unroll
    for (int mf = 0; mf < 2; mf++) {
        int mr = m0 + wm * 32 + mf * 16;
        int m1 = mr + gid, m2 = mr + gid + 8;
        float b1v = bias[m1], b2v = bias[m2];
        #pragma unroll
        for (int nf = 0; nf < 8; nf++) {
            int n = n0 + wn * 64 + nf * 8 + 2 * tg;
            if (n < N) {
                float2 v1 = make_float2(C[mf][nf][0] + b1v, C[mf][nf][1] + b1v);
                float2 v2 = make_float2(C[mf][nf][2] + b2v, C[mf][nf][3] + b2v);
                if (res) {
                    const float* rp = res + (long)bz * r_bs;
                    float2 r1 = *(const float2*)(rp + (long)m1 * N + n);
                    float2 r2 = *(const float2*)(rp + (long)m2 * N + n);
                    v1.x += r1.x; v1.y += r1.y; v2.x += r2.x; v2.y += r2.y;
                }
                *(float2*)(Y + (long)bz * y_bs + (long)m1 * N + n) = v1;
                *(float2*)(Y + (long)bz * y_bs + (long)m2 * N + n) = v2;
            }
        }
    }
}

// ---------------- tensor-core flash attention ----------------
// Block: 128 q-tile, one (b,h). 8 warps, each 16q x 64s. Online softmax warp-local.
// smem (floats): Qs[128c][136t], Ks[128c][72s], Vs[64vc][68s], Ps[64s][136q] (reused as Os[64vc][136t]).
#define QPAD 136
#define KPAD 72
#define VPAD 68
#define PPAD 136
#define ATT_Q (128*QPAD)
#define ATT_K (128*KPAD)
#define ATT_V (64*VPAD)
#define ATT_P (64*PPAD)
#define ATTN_BYTES ((ATT_Q + ATT_K + ATT_V + ATT_P) * 4)

__global__ __launch_bounds__(256, 1) void attn_tc(
    const float* __restrict__ Qc, long qc_bs,
    const float* __restrict__ Qp, long qp_bs,
    const float* __restrict__ Kc, long kc_bs,
    const float* __restrict__ Kp, long kp_bs,
    const float* __restrict__ V,  long v_bs,
    float* __restrict__ O, long o_bs,
    int Lq, int Ls, float sc2)
{
    extern __shared__ float sm[];
    float* Qs = sm;
    float* Ks = sm + ATT_Q;
    float* Vs = Ks + ATT_K;
    float* Ps = Vs + ATT_V;

    int hy = blockIdx.y;
    int bi = hy >> 3, h = hy & 7;
    int t0 = blockIdx.x << 7;
    int tid = threadIdx.x;
    int lane = tid & 31, warp = tid >> 5;
    int gid = lane >> 2, tg = lane & 3;
    int q0 = warp * 16;

    // Q tile, natural [c][t], pre-scaled
    const float* qcb = Qc + (long)bi * qc_bs + (long)(h * 64) * Lq + t0;
    const float* qpb = Qp + (long)bi * qp_bs + (long)(h * 64) * Lq + t0;
    for (int idx = tid; idx < 4096; idx += 256) {
        int c = idx >> 5, t4 = (idx & 31) << 2;
        float4 v = (c < 64) ? *(const float4*)(qcb + (long)c * Lq + t4)
                            : *(const float4*)(qpb + (long)(c - 64) * Lq + t4);
        v.x *= sc2; v.y *= sc2; v.z *= sc2; v.w *= sc2;
        *(float4*)&Qs[c * QPAD + t4] = v;
    }

    float m0r = -1e30f, m1r = -1e30f, l0 = 0.f, l1 = 0.f;
    float OC[8][4];
    #pragma unroll
    for (int i = 0; i < 8; i++)
        #pragma unroll
        for (int j = 0; j < 4; j++) OC[i][j] = 0.f;

    const float* kcb = Kc + (long)bi * kc_bs + (long)(h * 64) * Ls;
    const float* kpb = Kp + (long)bi * kp_bs + (long)(h * 64) * Ls;
    const float* vb  = V  + (long)bi * v_bs  + (long)(h * 64) * Ls;

    int nT = Ls >> 6;
    for (int it = 0; it < nT; it++) {
        int s0 = it << 6;
        __syncthreads();
        // K tile [c][s]
        for (int idx = tid; idx < 2048; idx += 256) {
            int c = idx >> 4, s4 = (idx & 15) << 2;
            float4 v = (c < 64) ? *(const float4*)(kcb + (long)c * Ls + s0 + s4)
                                : *(const float4*)(kpb + (long)(c - 64) * Ls + s0 + s4);
            *(float4*)&Ks[c * KPAD + s4] = v;
        }
        // V tile [vc][s]
        for (int idx = tid; idx < 1024; idx += 256) {
            int vc = idx >> 4, s4 = (idx & 15) << 2;
            float4 v = *(const float4*)(vb + (long)vc * Ls + s0 + s4);
            *(float4*)&Vs[vc * VPAD + s4] = v;
        }
        __syncthreads();

        // scores: warp computes S[16q][64s]
        float SC[8][4];
        #pragma unroll
        for (int i = 0; i < 8; i++)
            #pragma unroll
            for (int j = 0; j < 4; j++) SC[i][j] = 0.f;

        #pragma unroll
        for (int kf = 0; kf < 16; kf++) {
            int kk = kf * 8;
            uint32_t a[4];
            a[0] = __float_as_uint(Qs[(kk + tg) * QPAD + q0 + gid]);
            a[1] = __float_as_uint(Qs[(kk + tg) * QPAD + q0 + gid + 8]);
            a[2] = __float_as_uint(Qs[(kk + tg + 4) * QPAD + q0 + gid]);
            a[3] = __float_as_uint(Qs[(kk + tg + 4) * QPAD + q0 + gid + 8]);
            // NOTE: A fragment element (row=q, col=c) is Qs[c][t0q]: row index = q.
            // a0 needs (row=gid, col=tg) -> Qs[(kk+tg)*QPAD + q0+gid]  (as written)
            #pragma unroll
            for (int nf = 0; nf < 8; nf++) {
                uint32_t b0 = __float_as_uint(Ks[(kk + tg) * KPAD + nf * 8 + gid]);
                uint32_t b1 = __float_as_uint(Ks[(kk + tg + 4) * KPAD + nf * 8 + gid]);
                mma_tf32(SC[nf], a, b0, b1);
            }
        }

        // online softmax over the two rows this thread owns (gid, gid+8)
        float mx0 = -1e30f, mx1 = -1e30f;
        #pragma unroll
        for (int nf = 0; nf < 8; nf++) {
            mx0 = fmaxf(mx0, fmaxf(SC[nf][0], SC[nf][1]));
            mx1 = fmaxf(mx1, fmaxf(SC[nf][2], SC[nf][3]));
        }
        mx0 = fmaxf(mx0, __shfl_xor_sync(0xffffffffu, mx0, 1));
        mx0 = fmaxf(mx0, __shfl_xor_sync(0xffffffffu, mx0, 2));
        mx1 = fmaxf(mx1, __shfl_xor_sync(0xffffffffu, mx1, 1));
        mx1 = fmaxf(mx1, __shfl_xor_sync(0xffffffffu, mx1, 2));
        float mn0 = fmaxf(m0r, mx0), mn1 = fmaxf(m1r, mx1);
        float corr0 = __expf(m0r - mn0), corr1 = __expf(m1r - mn1);
        float rs0 = 0.f, rs1 = 0.f;
        #pragma unroll
        for (int nf = 0; nf < 8; nf++) {
            SC[nf][0] = __expf(SC[nf][0] - mn0);
            SC[nf][1] = __expf(SC[nf][1] - mn0);
            SC[nf][2] = __expf(SC[nf][2] - mn1);
            SC[nf][3] = __expf(SC[nf][3] - mn1);
            rs0 += SC[nf][0] + SC[nf][1];
            rs1 += SC[nf][2] + SC[nf][3];
        }
        rs0 += __shfl_xor_sync(0xffffffffu, rs0, 1);
        rs0 += __shfl_xor_sync(0xffffffffu, rs0, 2);
        rs1 += __shfl_xor_sync(0xffffffffu, rs1, 1);
        rs1 += __shfl_xor_sync(0xffffffffu, rs1, 2);
        l0 = l0 * corr0 + rs0;
        l1 = l1 * corr1 + rs1;
        m0r = mn0; m1r = mn1;
        #pragma unroll
        for (int nf = 0; nf < 8; nf++) {
            OC[nf][0] *= corr0; OC[nf][1] *= corr0;
            OC[nf][2] *= corr1; OC[nf][3] *= corr1;
        }

        // write P to smem [s][q]
        #pragma unroll
        for (int nf = 0; nf < 8; nf++) {
            int col = nf * 8 + 2 * tg;
            Ps[col * PPAD + q0 + gid]           = SC[nf][0];
            Ps[(col + 1) * PPAD + q0 + gid]     = SC[nf][1];
            Ps[col * PPAD + q0 + gid + 8]       = SC[nf][2];
            Ps[(col + 1) * PPAD + q0 + gid + 8] = SC[nf][3];
        }
        __syncwarp();

        // PV: O[16q][64vc] += P[16q][64s] @ V[64s][64vc]
        #pragma unroll
        for (int kf = 0; kf < 8; kf++) {
            int kk = kf * 8;
            uint32_t a[4];
            a[0] = __float_as_uint(Ps[(kk + tg) * PPAD + q0 + gid]);
            a[1] = __float_as_uint(Ps[(kk + tg) * PPAD + q0 + gid + 8]);
            a[2] = __float_as_uint(Ps[(kk + tg + 4) * PPAD + q0 + gid]);
            a[3] = __float_as_uint(Ps[(kk + tg + 4) * PPAD + q0 + gid + 8]);
            #pragma unroll
            for (int nf = 0; nf < 8; nf++) {
                uint32_t b0 = __float_as_uint(Vs[(nf * 8 + gid) * VPAD + kk + tg]);
                uint32_t b1 = __float_as_uint(Vs[(nf * 8 + gid) * VPAD + kk + tg + 4]);
                mma_tf32(OC[nf], a, b0, b1);
            }
        }
    }

    // normalize + transpose through smem (reuse Ps as Os[vc][136])
    __syncthreads();
    float inv0 = 1.f / l0, inv1 = 1.f / l1;
    float* Os = Ps;
    #pragma unroll
    for (int nf = 0; nf < 8; nf++) {
        int vc = nf * 8 + 2 * tg;
        Os[vc * PPAD + q0 + gid]           = OC[nf][0] * inv0;
        Os[(vc + 1) * PPAD + q0 + gid]     = OC[nf][1] * inv0;
        Os[vc * PPAD + q0 + gid + 8]       = OC[nf][2] * inv1;
        Os[(vc + 1) * PPAD + q0 + gid + 8] = OC[nf][3] * inv1;
    }
    __syncthreads();
    float* ob = O + (long)bi * o_bs + (long)(h * 64) * Lq + t0;
    for (int idx = tid; idx < 8192; idx += 256) {
        int c = idx >> 7, t = idx & 127;
        ob[(long)c * Lq + t] = Os[c * PPAD + t];
    }
}

// ---------------- launch ----------------
extern "C" void kernel_launch(void* const* d_in, const int* in_sizes, int n_in,
                              void* d_out, int out_size)
{
    const float* x           = (const float*)d_in[0];
    const float* xf_out      = (const float*)d_in[1];
    const float* obj_contour = (const float*)d_in[2];
    const float* obj_desc    = (const float*)d_in[3];
    const float* ipce        = (const float*)d_in[4];
    const float* gn_qkv_g    = (const float*)d_in[5];
    const float* gn_qkv_b    = (const float*)d_in[6];
    const float* W_self_qkv  = (const float*)d_in[7];
    const float* b_self_qkv  = (const float*)d_in[8];
    const float* W_cross_q   = (const float*)d_in[9];
    const float* b_cross_q   = (const float*)d_in[10];
    const float* W_content   = (const float*)d_in[11];
    const float* b_content   = (const float*)d_in[12];
    const float* W_pos       = (const float*)d_in[13];
    const float* b_pos       = (const float*)d_in[14];
    const float* gn_desc_g   = (const float*)d_in[15];
    const float* gn_desc_b   = (const float*)d_in[16];
    const float* gn_cpos_g   = (const float*)d_in[17];
    const float* gn_cpos_b   = (const float*)d_in[18];
    const float* gn_ipos_g   = (const float*)d_in[19];
    const float* gn_ipos_b   = (const float*)d_in[20];
    const float* W_self_out  = (const float*)d_in[21];
    const float* b_self_out  = (const float*)d_in[22];
    const float* W_cross_out = (const float*)d_in[23];
    const float* b_cross_out = (const float*)d_in[24];
    float* out = (float*)d_out;

    float *gn1, *qkv, *ipos, *attn, *xf2, *cpos, *content, *kv;
    cudaGetSymbolAddress((void**)&gn1,     g_gn1);
    cudaGetSymbolAddress((void**)&qkv,     g_qkv);
    cudaGetSymbolAddress((void**)&ipos,    g_ipos);
    cudaGetSymbolAddress((void**)&attn,    g_attnbuf);
    cudaGetSymbolAddress((void**)&xf2,     g_xf2);
    cudaGetSymbolAddress((void**)&cpos,    g_cpos);
    cudaGetSymbolAddress((void**)&content, g_content);
    cudaGetSymbolAddress((void**)&kv,      g_kv);
    float* cq = qkv;  // reuse: self qkv dead after steps 5/6

    cudaFuncSetAttribute(attn_tc, cudaFuncAttributeMaxDynamicSharedMemorySize,
                         ATTN_BYTES);

    const float sc2 = 0.08838834764831845f;  // 128^-0.5
    const float eps = 1e-5f;

    // 1. gn1 = GN(xf)
    gn_kernel<<<BB * 32, 256>>>(x, gn1, gn_qkv_g, gn_qkv_b, nullptr, 512, 16, 1024, eps);
    // 2. qkv = W_self_qkv @ gn1 + b
    gemm_tc<<<dim3(8, 12, BB), 256>>>(W_self_qkv, gn1, b_self_qkv, nullptr, qkv,
                                      1536, 1024, 512, 512L * 1024, 1536L * 1024, 0);
    // 3. ipos = W_pos @ ipce + b_pos
    gemm_tc<<<dim3(8, 4, BB), 256>>>(W_pos, ipce, b_pos, nullptr, ipos,
                                     512, 1024, 512, 512L * 1024, 512L * 1024, 0);
    // 4. ipos = GN(ipos) in-place
    gn_kernel<<<BB * 32, 256>>>(ipos, ipos, gn_ipos_g, gn_ipos_b, nullptr, 512, 16, 1024, eps);
    // 5. self attention
    attn_tc<<<dim3(8, 64), 256, ATTN_BYTES>>>(
        qkv, 1536L * 1024, ipos, 512L * 1024,
        qkv + 512L * 1024, 1536L * 1024, ipos, 512L * 1024,
        qkv + 1024L * 1024, 1536L * 1024,
        attn, 512L * 1024, 1024, 1024, sc2);
    // 6. xf2 = x + W_self_out @ attn + b
    gemm_tc<<<dim3(8, 4, BB), 256>>>(W_self_out, attn, b_self_out, x, xf2,
                                     512, 1024, 512, 512L * 1024, 512L * 1024, 512L * 1024);
    // 7. gn1 = GN(xf2)
    gn_kernel<<<BB * 32, 256>>>(xf2, gn1, gn_qkv_g, gn_qkv_b, nullptr, 512, 16, 1024, eps);
    // 8. cq = W_cross_q @ gn1 + b
    gemm_tc<<<dim3(8, 4, BB), 256>>>(W_cross_q, gn1, b_cross_q, nullptr, cq,
                                     512, 1024, 512, 512L * 1024, 512L * 1024, 0);
    // 9. cpos = W_pos @ obj_contour + b_pos
    gemm_tc<<<dim3(1, 4, BB), 256>>>(W_pos, obj_contour, b_pos, nullptr, cpos,
                                     512, 64, 512, 512L * 64, 512L * 64, 0);
    // 10. cpos = GN(cpos)
    gn_kernel<<<BB * 32, 256>>>(cpos, cpos, gn_cpos_g, gn_cpos_b, nullptr, 512, 16, 64, eps);
    // 11. content = (xf_out + GN(obj_desc)) / 2
    gn_kernel<<<BB * 32, 256>>>(obj_desc, content, gn_desc_g, gn_desc_b, xf_out, 512, 16, 64, eps);
    // 12. kv = W_content @ content + b
    gemm_tc<<<dim3(1, 8, BB), 256>>>(W_content, content, b_content, nullptr, kv,
                                     1024, 64, 512, 512L * 64, 1024L * 64, 0);
    // 13. cross attention (Ls = 64)
    attn_tc<<<dim3(8, 64), 256, ATTN_BYTES>>>(
        cq, 512L * 1024, ipos, 512L * 1024,
        kv, 1024L * 64, cpos, 512L * 64,
        kv + 512L * 64, 1024L * 64,
        attn, 512L * 1024, 1024, 64, sc2);
    // 14. out = xf2 + W_cross_out @ attn + b
    gemm_tc<<<dim3(8, 4, BB), 256>>>(W_cross_out, attn, b_cross_out, xf2, out,
                                     512, 1024, 512, 512L * 1024, 512L * 1024, 512L * 1024);
}